// round 16
// baseline (speedup 1.0000x reference)
#include <cuda_runtime.h>
#include <cuda_fp16.h>
#include <cstdint>

#define FLEN 1024
#define DDIM 1024
#define HALF 512            // steps per direction
#define NGRP 32             // blocks per direction
#define NBLK (2*NGRP)
#define TPB  512
#define TILE_BYTES 65536    // 32 vectors x 1024 halves x 2B per block per step
#define SENT 0x7FA00BADu    // qNaN payload; chain data is strictly positive

// dynamic smem layout
#define SMEM_SX    (3*TILE_BYTES)           // int[512]
#define SMEM_SP    (SMEM_SX + 2048)         // float[2][512] partials (dbl buf)
#define SMEM_WV    (SMEM_SP + 4096)         // float[16][64] backward w staging
#define SMEM_MBAR  (SMEM_WV + 4096)
#define SMEM_TOTAL (SMEM_MBAR + 64)

// SINGLE fp16 copy of core, tiled so BOTH directions read it and the whole
// 64MB working set stays L2-resident (the 128MB two-layout version thrashed
// DRAM every step). Layout: matrix c = 32x32 tiles of 32x32, tile (I,J) at
// tile-index I*32+J (row-major), within-tile [j'][i'] with i contiguous:
//   elem(c,i,j) = (c<<20) + ((i>>5)<<15) + ((j>>5)<<10) + ((j&31)<<5) + (i&31)
// Forward block fb: tiles (I=0..31, J=fb)  -> 32 chunks of 2KB, stride 64KB.
// Backward block bb: tiles (I=bb, J=0..31) -> ONE contiguous 64KB chunk.
__device__ __align__(128) __half g_cm[(size_t)32*1024*1024];

// WRITE-ONCE self-validating chain-vector buffers (R14-proven): every
// (step, element) location is written exactly once per launch; readers rely
// only on per-location coherence of naturally-aligned 4B accesses.
__device__ __align__(16) float g_bV[HALF][DDIM];
__device__ __align__(16) float g_bW[HALF][DDIM];

// ---------------- helpers ----------------
__device__ __forceinline__ float ld_vol_f32(const float* p) {
    float v;
    asm volatile("ld.volatile.global.f32 %0, [%1];" : "=f"(v) : "l"(p) : "memory");
    return v;
}
__device__ __forceinline__ void st_vol_f32(float* p, float v) {
    asm volatile("st.volatile.global.f32 [%0], %1;" :: "l"(p), "f"(v) : "memory");
}
__device__ __forceinline__ unsigned smem_u32(const void* p) {
    unsigned a;
    asm("{ .reg .u64 t; cvta.to.shared.u64 t, %1; cvt.u32.u64 %0, t; }"
        : "=r"(a) : "l"(p));
    return a;
}
__device__ __forceinline__ void mbar_init(unsigned a, unsigned cnt) {
    asm volatile("mbarrier.init.shared.b64 [%0], %1;" :: "r"(a), "r"(cnt) : "memory");
}
__device__ __forceinline__ void mbar_expect(unsigned a, unsigned tx) {
    asm volatile("mbarrier.arrive.expect_tx.shared.b64 _, [%0], %1;"
                 :: "r"(a), "r"(tx) : "memory");
}
__device__ __forceinline__ void bulk_g2s(unsigned dst, const void* src,
                                         unsigned bytes, unsigned mbar) {
    asm volatile("cp.async.bulk.shared::cluster.global.mbarrier::complete_tx::bytes "
                 "[%0], [%1], %2, [%3];"
                 :: "r"(dst), "l"(src), "r"(bytes), "r"(mbar) : "memory");
}
__device__ __forceinline__ void mbar_wait(unsigned a, unsigned ph) {
    unsigned done;
    asm volatile("{ .reg .pred p; "
                 "mbarrier.try_wait.parity.acquire.cta.shared::cta.b64 p, [%1], %2; "
                 "selp.b32 %0, 1, 0, p; }"
                 : "=r"(done) : "r"(a), "r"(ph) : "memory");
    if (!done) {
        asm volatile("{ .reg .pred P1; "
                     "W%=: mbarrier.try_wait.parity.acquire.cta.shared::cta.b64 P1, [%0], %1, 0x989680; "
                     "@P1 bra D%=; bra W%=; D%=: }"
                     :: "r"(a), "r"(ph) : "memory");
    }
}

// ---------------- init: sentinel-fill both buffers (every launch) ----------------
__global__ void init_kernel() {
    const unsigned tid = blockIdx.x * blockDim.x + threadIdx.x;
    const unsigned n = HALF * DDIM;
    const float s = __uint_as_float(SENT);
    for (unsigned i = tid; i < n; i += gridDim.x * blockDim.x) {
        st_vol_f32(&g_bV[0][0] + i, s);
        st_vol_f32(&g_bW[0][0] + i, s);
    }
}

// ---------------- pre-pass: fp32 -> tiled fp16 (single layout) ----------------
// grid = 32 matrices x 32 I-tiles x 32 J-tiles; block = 256 threads.
__global__ void __launch_bounds__(256, 4)
convert_kernel(const float* __restrict__ core)
{
    __shared__ float s[32][33];
    const int c = blockIdx.x >> 10;
    const int I = (blockIdx.x >> 5) & 31;
    const int J = blockIdx.x & 31;
    const int t = threadIdx.x;

    // phase 1: read the 32x32 fp32 tile (coalesced float4 over j)
    {
        const int ii = t >> 3, j4 = (t & 7) << 2;
        const float4 v = *reinterpret_cast<const float4*>(
            core + ((size_t)c << 20) + ((size_t)((I << 5) + ii) << 10) + (J << 5) + j4);
        s[ii][j4 + 0] = v.x; s[ii][j4 + 1] = v.y;
        s[ii][j4 + 2] = v.z; s[ii][j4 + 3] = v.w;
    }
    __syncthreads();

    // phase 2: write within-tile [j'][i'] halves (i contiguous)
    {
        const int jj = t >> 3, i4 = (t & 7) << 2;
        __half2 h0 = __floats2half2_rn(s[i4 + 0][jj], s[i4 + 1][jj]);
        __half2 h1 = __floats2half2_rn(s[i4 + 2][jj], s[i4 + 3][jj]);
        uint2 u = make_uint2(*reinterpret_cast<unsigned*>(&h0),
                             *reinterpret_cast<unsigned*>(&h1));
        *reinterpret_cast<uint2*>(
            &g_cm[((size_t)c << 20) + ((size_t)I << 15) + (J << 10) + (jj << 5) + i4]) = u;
    }
}

// ---------------- persistent chain kernel ----------------
__global__ void __launch_bounds__(TPB, 1)
tn_l2res_kernel(const int*   __restrict__ x,
                const float* __restrict__ lb,
                const float* __restrict__ rb,
                float*       __restrict__ out)
{
    extern __shared__ char smem[];
    int*   sx    = reinterpret_cast<int*>  (smem + SMEM_SX);
    float* spart = reinterpret_cast<float*>(smem + SMEM_SP);  // [2][512]
    float* swv   = reinterpret_cast<float*>(smem + SMEM_WV);  // [16][64]
    const unsigned sbase = smem_u32(smem);
    const unsigned mb0   = sbase + SMEM_MBAR;

    const int tid = threadIdx.x;
    const int b   = blockIdx.x;
    const int l   = tid & 31;
    const int w   = tid >> 5;      // 16 warps
    const bool fwd = (b < NGRP);
    const int  ob  = fwd ? b : b - NGRP;

    const __half* mat = g_cm;
    float (*buf)[DDIM] = fwd ? g_bV : g_bW;
    const float* bound = fwd ? lb : rb;

    if (tid == 0) {
        mbar_init(mb0, 1); mbar_init(mb0 + 8, 1); mbar_init(mb0 + 16, 1);
        asm volatile("fence.proxy.async.shared::cta;" ::: "memory");
    }
    if (fwd) { for (int t = tid; t < HALF; t += TPB) sx[t] = x[t]; }
    else     { for (int t = tid; t < HALF; t += TPB) sx[t] = x[FLEN - 1 - t]; }
    __syncthreads();

    // ---- prime tiles for steps 0 and 1 ----
    if (fwd) {
        if (w == 15) {
            #pragma unroll
            for (int s = 0; s < 2; ++s) {
                if (l == 0) mbar_expect(mb0 + s * 8, TILE_BYTES);
                __syncwarp();
                bulk_g2s(sbase + s * TILE_BYTES + (l << 11),
                         mat + (((size_t)sx[s]) << 20) + ((size_t)l << 15) + (ob << 10),
                         2048, mb0 + s * 8);
            }
        }
    } else if (tid == 0) {
        mbar_expect(mb0, TILE_BYTES);
        bulk_g2s(sbase, mat + (((size_t)sx[0]) << 20) + ((size_t)ob << 15),
                 TILE_BYTES, mb0);
        mbar_expect(mb0 + 8, TILE_BYTES);
        bulk_g2s(sbase + TILE_BYTES, mat + (((size_t)sx[1]) << 20) + ((size_t)ob << 15),
                 TILE_BYTES, mb0 + 8);
    }

    if (fwd) {
        // ======== forward: v_j <- sum_i v_i M[i][j]; block owns j in [32ob,+32) ========
        const int g = l >> 3;        // local column group 0..3
        const int r = l & 7;         // i-octet within warp segment
        const int fourR = r << 2;
        const int q = (w << 3) + r;  // i-octet index: i in [8q, 8q+8)

        for (int t = 0; t < HALF; ++t) {
            const int slot = t % 3;
            mbar_wait(mb0 + slot * 8, (unsigned)((t / 3) & 1));

            // pre-poll: load + convert matrix quads (same halves, same order
            // as R15 -> forward chain bit-identical)
            const char* tile = smem + slot * TILE_BYTES;
            float4 ma[8], mbq[8];
            #pragma unroll
            for (int k = 0; k < 8; ++k) {
                const int c = (k << 2) + g;
                const uint4 qv = *reinterpret_cast<const uint4*>(
                    tile + ((q >> 2) << 11) + (c << 6) + ((q & 3) << 4));
                float2 f;
                f = __half22float2(*reinterpret_cast<const __half2*>(&qv.x));
                ma[k].x = f.x; ma[k].y = f.y;
                f = __half22float2(*reinterpret_cast<const __half2*>(&qv.y));
                ma[k].z = f.x; ma[k].w = f.y;
                f = __half22float2(*reinterpret_cast<const __half2*>(&qv.z));
                mbq[k].x = f.x; mbq[k].y = f.y;
                f = __half22float2(*reinterpret_cast<const __half2*>(&qv.w));
                mbq[k].z = f.x; mbq[k].w = f.y;
            }

            // queue TMA for step t+2: warp15's 32 lanes issue the 32 chunks
            if (w == 15 && t + 2 < HALF) {
                const int s2 = (t + 2) % 3;
                if (l == 0) mbar_expect(mb0 + s2 * 8, TILE_BYTES);
                __syncwarp();
                bulk_g2s(sbase + s2 * TILE_BYTES + (l << 11),
                         mat + (((size_t)sx[t + 2]) << 20) + ((size_t)l << 15) + (ob << 10),
                         2048, mb0 + s2 * 8);
            }

            // poll BOTH records concurrently (one RTT, not two)
            float2 myv;
            if (t == 0) {
                myv = *reinterpret_cast<const float2*>(bound + (tid << 1));
            } else {
                const float* src = &buf[t - 1][tid << 1];
                do {
                    myv.x = ld_vol_f32(src);
                    myv.y = ld_vol_f32(src + 1);
                } while (__float_as_uint(myv.x) == SENT ||
                         __float_as_uint(myv.y) == SENT);
            }
            float4 va, vb;
            va.x = __shfl_sync(0xffffffffu, myv.x, fourR);
            va.y = __shfl_sync(0xffffffffu, myv.y, fourR);
            va.z = __shfl_sync(0xffffffffu, myv.x, fourR + 1);
            va.w = __shfl_sync(0xffffffffu, myv.y, fourR + 1);
            vb.x = __shfl_sync(0xffffffffu, myv.x, fourR + 2);
            vb.y = __shfl_sync(0xffffffffu, myv.y, fourR + 2);
            vb.z = __shfl_sync(0xffffffffu, myv.x, fourR + 3);
            vb.w = __shfl_sync(0xffffffffu, myv.y, fourR + 3);

            float acc[8];
            #pragma unroll
            for (int k = 0; k < 8; ++k) {
                float s = 0.f;
                s = fmaf(ma[k].x, va.x, s);  s = fmaf(ma[k].y, va.y, s);
                s = fmaf(ma[k].z, va.z, s);  s = fmaf(ma[k].w, va.w, s);
                s = fmaf(mbq[k].x, vb.x, s); s = fmaf(mbq[k].y, vb.y, s);
                s = fmaf(mbq[k].z, vb.z, s); s = fmaf(mbq[k].w, vb.w, s);
                acc[k] = s;
            }
            #pragma unroll
            for (int k = 0; k < 8; ++k) {
                #pragma unroll
                for (int off = 1; off < 8; off <<= 1)
                    acc[k] += __shfl_xor_sync(0xffffffffu, acc[k], off);
            }
            float* sp = spart + ((t & 1) << 9);
            if (r == 0) {
                #pragma unroll
                for (int k = 0; k < 8; ++k) sp[(w << 5) + (k << 2) + g] = acc[k];
            }
            __syncthreads();

            if (tid < 32) {
                float s = 0.f;
                #pragma unroll
                for (int w2 = 0; w2 < 16; ++w2) s += sp[(w2 << 5) + tid];
                st_vol_f32(&buf[t][(ob << 5) + tid], s);
            }
        }
    } else {
        // ======== backward: u_i <- sum_j M[i][j] w_j; block owns i in [32ob,+32) ========
        const int p  = l & 15;       // output i-pair: i_local = 2p, 2p+1
        const int hi = l >> 4;       // j parity half
        float* swv_w = swv + (w << 6);

        for (int t = 0; t < HALF; ++t) {
            const int slot = t % 3;
            mbar_wait(mb0 + slot * 8, (unsigned)((t / 3) & 1));

            // pre-poll: load + convert this lane's 32 (i-pair, j) half2s.
            // smem slot = tiles (ob, J=0..31); elem (j, i') at byte
            // (J<<11) + (j&31)<<6 + i'<<1; warp covers j in [64w, 64w+64).
            const char* tile = smem + slot * TILE_BYTES;
            const char* base2w = tile + (w << 12);   // J = 2w
            float2 fm[32];
            #pragma unroll
            for (int a = 0; a < 32; ++a) {
                const int jj = (a << 1) + hi;        // local j in [0,64)
                const unsigned qv = *reinterpret_cast<const unsigned*>(
                    base2w + ((jj >> 5) << 11) + ((jj & 31) << 6) + (p << 2));
                fm[a] = __half22float2(*reinterpret_cast<const __half2*>(&qv));
            }

            // queue TMA for step t+2 (single contiguous 64KB chunk)
            if (w == 15 && l == 0 && t + 2 < HALF) {
                const int s2 = (t + 2) % 3;
                mbar_expect(mb0 + s2 * 8, TILE_BYTES);
                bulk_g2s(sbase + s2 * TILE_BYTES,
                         mat + (((size_t)sx[t + 2]) << 20) + ((size_t)ob << 15),
                         TILE_BYTES, mb0 + s2 * 8);
            }

            // poll BOTH records concurrently
            float2 myv;
            if (t == 0) {
                myv = *reinterpret_cast<const float2*>(bound + (tid << 1));
            } else {
                const float* src = &buf[t - 1][tid << 1];
                do {
                    myv.x = ld_vol_f32(src);
                    myv.y = ld_vol_f32(src + 1);
                } while (__float_as_uint(myv.x) == SENT ||
                         __float_as_uint(myv.y) == SENT);
            }

            // stage warp's 64 w-elements; broadcast-gather during FMA
            *reinterpret_cast<float2*>(&swv_w[l << 1]) = myv;
            __syncwarp();
            float acc0 = 0.f, acc1 = 0.f;
            #pragma unroll
            for (int a = 0; a < 32; ++a) {
                const float wj = swv_w[(a << 1) + hi];
                acc0 = fmaf(fm[a].x, wj, acc0);
                acc1 = fmaf(fm[a].y, wj, acc1);
            }
            acc0 += __shfl_xor_sync(0xffffffffu, acc0, 16);
            acc1 += __shfl_xor_sync(0xffffffffu, acc1, 16);

            float* sp = spart + ((t & 1) << 9);
            if (hi == 0) {
                sp[(w << 5) + (p << 1)]     = acc0;
                sp[(w << 5) + (p << 1) + 1] = acc1;
            }
            __syncthreads();

            if (tid < 32) {
                float s = 0.f;
                #pragma unroll
                for (int w2 = 0; w2 < 16; ++w2) s += sp[(w2 << 5) + tid];
                st_vol_f32(&buf[t][(ob << 5) + tid], s);
            }
        }
    }

    // ---- final combine: block 0 polls both final vectors, dots them ----
    if (b == 0) {
        const float* pv = &g_bV[HALF - 1][tid << 1];
        const float* pw = &g_bW[HALF - 1][tid << 1];
        float2 vf, wf;
        do { vf.x = ld_vol_f32(pv); vf.y = ld_vol_f32(pv + 1); }
        while (__float_as_uint(vf.x) == SENT || __float_as_uint(vf.y) == SENT);
        do { wf.x = ld_vol_f32(pw); wf.y = ld_vol_f32(pw + 1); }
        while (__float_as_uint(wf.x) == SENT || __float_as_uint(wf.y) == SENT);
        float part = vf.x * wf.x + vf.y * wf.y;
        #pragma unroll
        for (int off = 16; off > 0; off >>= 1)
            part += __shfl_xor_sync(0xffffffffu, part, off);
        __syncthreads();              // spart fully consumed by main loop
        if (l == 0) spart[w] = part;
        __syncthreads();
        if (tid == 0) {
            float s = 0.f;
            #pragma unroll
            for (int w2 = 0; w2 < 16; ++w2) s += spart[w2];
            out[0] = s;
        }
    }
}

extern "C" void kernel_launch(void* const* d_in, const int* in_sizes, int n_in,
                              void* d_out, int out_size) {
    const int*   x    = (const int*)  d_in[0];  // int32[1024]
    const float* core = (const float*)d_in[1];  // f32[32,1024,1024]
    const float* lb   = (const float*)d_in[2];  // f32[1024]
    const float* rb   = (const float*)d_in[3];  // f32[1024]
    float*       out  = (float*)d_out;

    cudaFuncSetAttribute(tn_l2res_kernel,
                         cudaFuncAttributeMaxDynamicSharedMemorySize, SMEM_TOTAL);
    init_kernel<<<128, 512>>>();
    convert_kernel<<<32 * 32 * 32, 256>>>(core);
    tn_l2res_kernel<<<NBLK, TPB, SMEM_TOTAL>>>(x, lb, rb, out);
}